// round 1
// baseline (speedup 1.0000x reference)
#include <cuda_runtime.h>
#include <cuda_bf16.h>
#include <math.h>

#define BB 512
#define TT 64
#define HH 512
#define VV 780
#define N_AT 40
#define KC 4
#define MAX_NB 8
#define NMSG (BB*TT+1)
#define BT (BB*TT)
#define NSTOP (BT+BB)
#define H2 (2*HH)

// ---------------- device scratch (static, no runtime allocation) ----------------
__device__ float g_table [NMSG*HH];   // message table h
__device__ float g_tableU[NMSG*HH];   // table @ U_r_w
__device__ float g_xall  [BT*HH];     // x features per (b,t)
__device__ float g_rootx [BB*HH];
__device__ float g_Xz    [BT*HH];     // x @ Wz_x + bz
__device__ float g_Xr    [BT*HH];     // x @ Wr + br
__device__ float g_Xh    [BT*HH];     // x @ Wh_x + bh
__device__ float g_sumh  [BB*HH];
__device__ float g_sumg  [BB*HH];
__device__ float g_stopA [NSTOP*H2];  // [x ; o] concatenated
__device__ float g_predH [BT*HH];
__device__ float g_predS [BT*VV];
__device__ float g_score [NSTOP];
__device__ float g_red   [8];         // 0 ce_sum, 1 pred_correct, 2 pmask_cnt, 3 stop_loss, 4 stop_correct

__device__ __forceinline__ float sigf(float x){ return 1.f/(1.f+expf(-x)); }

// ---------------- x features: sum node_rep over clique atoms ----------------
__global__ void k_xfeat(const float* __restrict__ node_rep,
                        const int* __restrict__ cidx,
                        const int* __restrict__ rcidx)
{
    int i = blockIdx.x; int c = threadIdx.x;
    if (i < BT) {
        int b = i / TT;
        const int* ci = cidx + (size_t)i*KC;
        float s0=0.f, s1=0.f;
        #pragma unroll
        for (int k=0;k<KC;k++){
            const float* nr = node_rep + ((size_t)b*N_AT + ci[k])*HH;
            s0 += nr[c]; s1 += nr[c+256];
        }
        g_xall[(size_t)i*HH + c]       = s0;
        g_xall[(size_t)i*HH + c + 256] = s1;
    } else {
        int b = i - BT;
        const int* ci = rcidx + (size_t)b*KC;
        float s0=0.f, s1=0.f;
        #pragma unroll
        for (int k=0;k<KC;k++){
            const float* nr = node_rep + ((size_t)b*N_AT + ci[k])*HH;
            s0 += nr[c]; s1 += nr[c+256];
        }
        g_rootx[b*HH + c]       = s0;
        g_rootx[b*HH + c + 256] = s1;
    }
}

// ---------------- big SGEMM: 128x128x8 tiles, 256 thr, 8x8 microtile ----------------
// EPI: 0 = C = acc + bias ; 1 = C = relu(acc+bias) ; 2 = no C store, relu + partial dot
//      with vector us accumulated atomically into g_score (stop head)
template<int EPI>
__global__ void sgemm_big(const float* __restrict__ A, int lda,
                          const float* __restrict__ Bm, int ldb,
                          const float* __restrict__ bias,
                          float* __restrict__ C, int ldc,
                          int M, int N, int K,
                          const float* __restrict__ us)
{
    __shared__ float sm[8*132 + 8*128];
    float (*As)[132] = (float(*)[132])sm;
    float (*Bs)[128] = (float(*)[128])(sm + 8*132);

    int t = threadIdx.x;
    int arow = t >> 1, ak = (t & 1) * 4;
    int bk = t >> 5, bcol = (t & 31) * 4;
    int tx = t & 15, ty = t >> 4;
    const float* Ab = A + (size_t)(blockIdx.y * 128) * lda;
    int gcolb = blockIdx.x * 128;

    float acc[8][8];
    #pragma unroll
    for (int i=0;i<8;i++)
        #pragma unroll
        for (int j=0;j<8;j++) acc[i][j]=0.f;

    for (int kt = 0; kt < K; kt += 8) {
        float4 av = *(const float4*)(Ab + (size_t)arow*lda + kt + ak);
        As[ak+0][arow]=av.x; As[ak+1][arow]=av.y; As[ak+2][arow]=av.z; As[ak+3][arow]=av.w;
        int gc = gcolb + bcol;
        float4 bv = make_float4(0.f,0.f,0.f,0.f);
        if (gc < N) bv = *(const float4*)(Bm + (size_t)(kt+bk)*ldb + gc);
        *(float4*)&Bs[bk][bcol] = bv;
        __syncthreads();
        #pragma unroll
        for (int k=0;k<8;k++){
            float4 a0 = *(const float4*)&As[k][ty*8];
            float4 a1 = *(const float4*)&As[k][ty*8+4];
            float4 b0 = *(const float4*)&Bs[k][tx*8];
            float4 b1 = *(const float4*)&Bs[k][tx*8+4];
            float a[8] = {a0.x,a0.y,a0.z,a0.w,a1.x,a1.y,a1.z,a1.w};
            float b[8] = {b0.x,b0.y,b0.z,b0.w,b1.x,b1.y,b1.z,b1.w};
            #pragma unroll
            for (int i=0;i<8;i++)
                #pragma unroll
                for (int j=0;j<8;j++) acc[i][j] += a[i]*b[j];
        }
        __syncthreads();
    }

    int row0 = blockIdx.y*128 + ty*8;
    int col0 = blockIdx.x*128 + tx*8;
    if (EPI == 2) {
        float part[8];
        #pragma unroll
        for (int i=0;i<8;i++){
            part[i]=0.f;
            #pragma unroll
            for (int j=0;j<8;j++){
                int col = col0 + j;
                if (col < N){
                    float cc = acc[i][j] + bias[col];
                    cc = cc > 0.f ? cc : 0.f;
                    part[i] += cc * us[col];
                }
            }
        }
        float* red = sm; // 128*16 floats fits
        #pragma unroll
        for (int i=0;i<8;i++) red[(ty*8+i)*16 + tx] = part[i];
        __syncthreads();
        if (t < 128){
            float s = 0.f;
            #pragma unroll
            for (int q=0;q<16;q++) s += red[t*16+q];
            atomicAdd(&g_score[blockIdx.y*128 + t], s);
        }
    } else {
        #pragma unroll
        for (int i=0;i<8;i++){
            #pragma unroll
            for (int j=0;j<8;j++){
                int col = col0 + j;
                if (col < N){
                    float cc = acc[i][j] + bias[col];
                    if (EPI == 1) cc = cc > 0.f ? cc : 0.f;
                    C[(size_t)(row0+i)*ldc + col] = cc;
                }
            }
        }
    }
}

// ---------------- small SGEMM: 64x64x16 tiles (M=N=512) ----------------
__global__ void sgemm_small(const float* __restrict__ A, int lda,
                            const float* __restrict__ Bm, int ldb,
                            float* __restrict__ C, int ldc, int K)
{
    __shared__ float As[64][17];
    __shared__ float Bs[16][64];
    int t = threadIdx.x;
    int arow = t >> 2, ak4 = (t & 3) * 4;
    int bk = t >> 4, bc4 = (t & 15) * 4;
    int tx = t & 15, ty = t >> 4;
    const float* Ab = A + (size_t)(blockIdx.y * 64) * lda;
    const float* Bb = Bm + blockIdx.x * 64;
    float acc[4][4];
    #pragma unroll
    for (int i=0;i<4;i++)
        #pragma unroll
        for (int j=0;j<4;j++) acc[i][j]=0.f;

    for (int kt = 0; kt < K; kt += 16) {
        float4 av = *(const float4*)(Ab + (size_t)arow*lda + kt + ak4);
        As[arow][ak4+0]=av.x; As[arow][ak4+1]=av.y; As[arow][ak4+2]=av.z; As[arow][ak4+3]=av.w;
        float4 bv = *(const float4*)(Bb + (size_t)(kt+bk)*ldb + bc4);
        *(float4*)&Bs[bk][bc4] = bv;
        __syncthreads();
        #pragma unroll
        for (int k=0;k<16;k++){
            float a[4];
            #pragma unroll
            for (int i=0;i<4;i++) a[i] = As[ty*4+i][k];
            float4 b = *(const float4*)&Bs[k][tx*4];
            float bb[4]={b.x,b.y,b.z,b.w};
            #pragma unroll
            for (int i=0;i<4;i++)
                #pragma unroll
                for (int j=0;j<4;j++) acc[i][j] += a[i]*bb[j];
        }
        __syncthreads();
    }
    #pragma unroll
    for (int i=0;i<4;i++)
        #pragma unroll
        for (int j=0;j<4;j++)
            C[(size_t)(blockIdx.y*64+ty*4+i)*ldc + blockIdx.x*64 + tx*4 + j] = acc[i][j];
}

// ---------------- per-step gather: sum_h, sum_g ----------------
__global__ void k_gather(int tstep, const int* __restrict__ nei_h)
{
    int b = blockIdx.x;
    int c = blockIdx.y*256 + threadIdx.x;
    const int* idx = nei_h + (size_t)(b*TT + tstep)*MAX_NB;
    float xr = g_Xr[(size_t)(b*TT + tstep)*HH + c];
    float ah = 0.f, ag = 0.f;
    #pragma unroll
    for (int n=0;n<MAX_NB;n++){
        size_t base = (size_t)idx[n]*HH + c;
        float hv = g_table[base];
        float uv = g_tableU[base];
        ah += hv;
        ag += hv * sigf(xr + uv);
    }
    g_sumh[b*HH + c] = ah;
    g_sumg[b*HH + c] = ag;
}

// ---------------- per-step dual GEMM + GRU epilogue ----------------
__global__ void k_gru(int tstep, const float* __restrict__ Bz, const float* __restrict__ Bh)
{
    __shared__ float As1[64][17], As2[64][17];
    __shared__ float Bs1[16][64], Bs2[16][64];
    int t = threadIdx.x;
    int arow = t >> 2, ak4 = (t & 3) * 4;
    int bk = t >> 4, bc4 = (t & 15) * 4;
    int tx = t & 15, ty = t >> 4;
    const float* A1 = g_sumh + (size_t)(blockIdx.y*64)*HH;
    const float* A2 = g_sumg + (size_t)(blockIdx.y*64)*HH;
    const float* B1 = Bz + blockIdx.x*64;
    const float* B2 = Bh + blockIdx.x*64;
    float acc1[4][4], acc2[4][4];
    #pragma unroll
    for (int i=0;i<4;i++)
        #pragma unroll
        for (int j=0;j<4;j++){ acc1[i][j]=0.f; acc2[i][j]=0.f; }

    for (int kt = 0; kt < HH; kt += 16) {
        float4 a1 = *(const float4*)(A1 + (size_t)arow*HH + kt + ak4);
        float4 a2 = *(const float4*)(A2 + (size_t)arow*HH + kt + ak4);
        As1[arow][ak4+0]=a1.x; As1[arow][ak4+1]=a1.y; As1[arow][ak4+2]=a1.z; As1[arow][ak4+3]=a1.w;
        As2[arow][ak4+0]=a2.x; As2[arow][ak4+1]=a2.y; As2[arow][ak4+2]=a2.z; As2[arow][ak4+3]=a2.w;
        float4 b1 = *(const float4*)(B1 + (size_t)(kt+bk)*HH + bc4);
        float4 b2 = *(const float4*)(B2 + (size_t)(kt+bk)*HH + bc4);
        *(float4*)&Bs1[bk][bc4] = b1;
        *(float4*)&Bs2[bk][bc4] = b2;
        __syncthreads();
        #pragma unroll
        for (int k=0;k<16;k++){
            float a1r[4], a2r[4];
            #pragma unroll
            for (int i=0;i<4;i++){ a1r[i]=As1[ty*4+i][k]; a2r[i]=As2[ty*4+i][k]; }
            float4 bv1 = *(const float4*)&Bs1[k][tx*4];
            float4 bv2 = *(const float4*)&Bs2[k][tx*4];
            float b1r[4]={bv1.x,bv1.y,bv1.z,bv1.w};
            float b2r[4]={bv2.x,bv2.y,bv2.z,bv2.w};
            #pragma unroll
            for (int i=0;i<4;i++)
                #pragma unroll
                for (int j=0;j<4;j++){
                    acc1[i][j] += a1r[i]*b1r[j];
                    acc2[i][j] += a2r[i]*b2r[j];
                }
        }
        __syncthreads();
    }
    #pragma unroll
    for (int i=0;i<4;i++){
        int row = blockIdx.y*64 + ty*4 + i;
        #pragma unroll
        for (int j=0;j<4;j++){
            int col = blockIdx.x*64 + tx*4 + j;
            size_t xi = (size_t)(row*TT + tstep)*HH + col;
            float z  = sigf(g_Xz[xi] + acc1[i][j]);
            float ph = tanhf(g_Xh[xi] + acc2[i][j]);
            float sh = g_sumh[(size_t)row*HH + col];
            g_table[(size_t)(row*TT + tstep + 1)*HH + col] = (1.f - z)*sh + z*ph;
        }
    }
}

// ---------------- deferred o gather + concat into stopA ----------------
__global__ void k_oall(const int* __restrict__ nei_o, const int* __restrict__ root_nei)
{
    int i = blockIdx.x;
    int c = blockIdx.y*256 + threadIdx.x;
    if (i < BT) {
        int tt = i % TT;
        float xv = g_xall[(size_t)i*HH + c];
        const int* idx = nei_o + (size_t)i*MAX_NB;
        float o = 0.f;
        #pragma unroll
        for (int n=0;n<MAX_NB;n++){
            int id = idx[n];
            if (id > 0 && ((id-1) % TT) < tt) o += g_table[(size_t)id*HH + c];
        }
        g_stopA[(size_t)i*H2 + c]      = xv;
        g_stopA[(size_t)i*H2 + HH + c] = o;
    } else {
        int b = i - BT;
        float xv = g_rootx[b*HH + c];
        const int* idx = root_nei + (size_t)b*MAX_NB;
        float o = 0.f;
        #pragma unroll
        for (int n=0;n<MAX_NB;n++) o += g_table[(size_t)idx[n]*HH + c];
        g_stopA[(size_t)i*H2 + c]      = xv;
        g_stopA[(size_t)i*H2 + HH + c] = o;
    }
}

// ---------------- stop loss / acc ----------------
__global__ void k_stoploss(const int* __restrict__ direction, const float* __restrict__ usb)
{
    int i = blockIdx.x*256 + threadIdx.x;
    float li = 0.f, ci = 0.f;
    if (i < NSTOP){
        float s = g_score[i] + usb[0];
        float tgt = (i < BT) ? (float)direction[i] : 0.f;
        float sp = (s > 0.f) ? (s + log1pf(expf(-s))) : log1pf(expf(s));
        li = sp - s*tgt;
        float pred = (s >= 0.f) ? 1.f : 0.f;
        ci = (pred == tgt) ? 1.f : 0.f;
    }
    __shared__ float rl[256], rc[256];
    rl[threadIdx.x]=li; rc[threadIdx.x]=ci;
    __syncthreads();
    for (int st=128; st>0; st>>=1){
        if (threadIdx.x < st){ rl[threadIdx.x]+=rl[threadIdx.x+st]; rc[threadIdx.x]+=rc[threadIdx.x+st]; }
        __syncthreads();
    }
    if (threadIdx.x==0){
        atomicAdd(&g_red[3], rl[0]);
        atomicAdd(&g_red[4], rc[0]);
    }
}

// ---------------- pred head CE / acc (per-row softmax) ----------------
__global__ void k_ce(const int* __restrict__ direction, const int* __restrict__ target)
{
    int i = blockIdx.x;
    int t = threadIdx.x;
    const float* S = g_predS + (size_t)i*VV;
    float val[4];
    float lmax = -1e30f; int lidx = 0;
    #pragma unroll
    for (int r=0;r<4;r++){
        int v = t + 256*r;
        if (v < VV){
            float x = S[v];
            val[r] = x;
            if (x > lmax){ lmax = x; lidx = v; }
        } else val[r] = -1e30f;
    }
    __shared__ float smax[256]; __shared__ int sidx[256];
    smax[t]=lmax; sidx[t]=lidx;
    __syncthreads();
    for (int st=128; st>0; st>>=1){
        if (t < st){
            float o = smax[t+st]; int oi = sidx[t+st];
            if (o > smax[t] || (o == smax[t] && oi < sidx[t])){ smax[t]=o; sidx[t]=oi; }
        }
        __syncthreads();
    }
    float m = smax[0]; int am = sidx[0];
    __syncthreads();
    float se = 0.f;
    #pragma unroll
    for (int r=0;r<4;r++){
        int v = t + 256*r;
        if (v < VV) se += expf(val[r] - m);
    }
    __shared__ float ssum[256];
    ssum[t]=se;
    __syncthreads();
    for (int st=128; st>0; st>>=1){
        if (t < st) ssum[t]+=ssum[t+st];
        __syncthreads();
    }
    if (t==0){
        float lse = m + logf(ssum[0]);
        int tg = target[i];
        float ce = lse - S[tg];
        float msk = (direction[i]==1) ? 1.f : 0.f;
        atomicAdd(&g_red[0], ce*msk);
        atomicAdd(&g_red[1], (am==tg) ? msk : 0.f);
        atomicAdd(&g_red[2], msk);
    }
}

__global__ void k_final(float* out)
{
    out[0] = g_red[0] / (float)BB;
    out[1] = g_red[3] / (float)BB;
    out[2] = g_red[1] / g_red[2];
    out[3] = g_red[4] / (float)NSTOP;
}

// ---------------- host launch ----------------
extern "C" void kernel_launch(void* const* d_in, const int* in_sizes, int n_in,
                              void* d_out, int out_size)
{
    const float* node_rep = (const float*)d_in[0];
    const int*   clique   = (const int*)  d_in[1];
    const int*   rclique  = (const int*)  d_in[2];
    const int*   nei_h    = (const int*)  d_in[3];
    const int*   nei_o    = (const int*)  d_in[4];
    const int*   rnei     = (const int*)  d_in[5];
    const int*   dir      = (const int*)  d_in[6];
    const int*   ptgt     = (const int*)  d_in[7];
    const float* Wz  = (const float*)d_in[8];
    const float* Wzb = (const float*)d_in[9];
    const float* Wr  = (const float*)d_in[10];
    const float* Wrb = (const float*)d_in[11];
    const float* Ur  = (const float*)d_in[12];
    const float* Wh  = (const float*)d_in[13];
    const float* Whb = (const float*)d_in[14];
    const float* Ww  = (const float*)d_in[15];
    const float* Wwb = (const float*)d_in[16];
    const float* Uw  = (const float*)d_in[17];
    const float* Ub  = (const float*)d_in[18];
    const float* Wo  = (const float*)d_in[19];
    const float* Wob = (const float*)d_in[20];
    const float* Us  = (const float*)d_in[21];
    const float* Usb = (const float*)d_in[22];

    float *tb, *tbU, *xall, *rootx, *Xz, *Xr, *Xh, *stopA, *predH, *predS, *score, *red;
    cudaGetSymbolAddress((void**)&tb,    g_table);
    cudaGetSymbolAddress((void**)&tbU,   g_tableU);
    cudaGetSymbolAddress((void**)&xall,  g_xall);
    cudaGetSymbolAddress((void**)&rootx, g_rootx);
    cudaGetSymbolAddress((void**)&Xz,    g_Xz);
    cudaGetSymbolAddress((void**)&Xr,    g_Xr);
    cudaGetSymbolAddress((void**)&Xh,    g_Xh);
    cudaGetSymbolAddress((void**)&stopA, g_stopA);
    cudaGetSymbolAddress((void**)&predH, g_predH);
    cudaGetSymbolAddress((void**)&predS, g_predS);
    cudaGetSymbolAddress((void**)&score, g_score);
    cudaGetSymbolAddress((void**)&red,   g_red);

    // reset per-launch state (messages must read as 0 before being written)
    cudaMemsetAsync(tb,   0, sizeof(float)*(size_t)NMSG*HH);
    cudaMemsetAsync(tbU,  0, sizeof(float)*(size_t)NMSG*HH);
    cudaMemsetAsync(score,0, sizeof(float)*NSTOP);
    cudaMemsetAsync(red,  0, sizeof(float)*8);

    // x features
    k_xfeat<<<BT+BB, 256>>>(node_rep, clique, rclique);

    // hoisted time-independent x projections
    dim3 gX(HH/128, BT/128);
    sgemm_big<0><<<gX, 256>>>(xall, HH, Wz, HH, Wzb, Xz, HH, BT, HH, HH, nullptr);
    sgemm_big<0><<<gX, 256>>>(xall, HH, Wr, HH, Wrb, Xr, HH, BT, HH, HH, nullptr);
    sgemm_big<0><<<gX, 256>>>(xall, HH, Wh, HH, Whb, Xh, HH, BT, HH, HH, nullptr);

    const float* Wzh = Wz + (size_t)HH*HH;  // rows H..2H of W_z (sum_h part)
    const float* Whh = Wh + (size_t)HH*HH;  // rows H..2H of W_h (sum_g part)

    // sequential scan
    for (int t = 0; t < TT; t++){
        k_gather<<<dim3(BB,2), 256>>>(t, nei_h);
        k_gru<<<dim3(8,8), 256>>>(t, Wzh, Whh);
        sgemm_small<<<dim3(8,8), 256>>>(tb + (size_t)(t+1)*HH, TT*HH,
                                        Ur, HH,
                                        tbU + (size_t)(t+1)*HH, TT*HH, HH);
    }

    // stop head
    k_oall<<<dim3(NSTOP,2), 256>>>(nei_o, rnei);
    sgemm_big<2><<<dim3(HH/128, NSTOP/128), 256>>>(stopA, H2, Uw, HH, Ub,
                                                   nullptr, 0, NSTOP, HH, H2, Us);
    k_stoploss<<<NSTOP/256, 256>>>(dir, Usb);

    // pred head: new_h rows are table rows 1..BT (contiguous)
    sgemm_big<1><<<dim3(HH/128, BT/128), 256>>>(tb + HH, HH, Ww, HH, Wwb,
                                                predH, HH, BT, HH, HH, nullptr);
    sgemm_big<0><<<dim3((VV+127)/128, BT/128), 256>>>(predH, HH, Wo, VV, Wob,
                                                      predS, VV, BT, VV, HH, nullptr);
    k_ce<<<BT, 256>>>(dir, ptgt);

    k_final<<<1,1>>>((float*)d_out);
}